// round 5
// baseline (speedup 1.0000x reference)
#include <cuda_runtime.h>
#include <math.h>
#include <stdint.h>

#define DIM   1536
#define SEQ   4096
#define HEADS 12
#define HD    128
#define CC    64
#define ATTN_SCALE 0.08838834764831845f   // 1/sqrt(128)

// ---------------- scratch ----------------------------------------------------
__device__ float g_q[SEQ * DIM];
__device__ float g_k[SEQ * DIM];
__device__ float g_v[SEQ * DIM];
__device__ float g_attn[SEQ * DIM];
__device__ float g_cos[SEQ * CC];
__device__ float g_sin[SEQ * CC];

// ---------------- helpers ----------------------------------------------------
__device__ __forceinline__ uint32_t f2tf(float x) {
    uint32_t r; asm("cvt.rna.tf32.f32 %0, %1;" : "=r"(r) : "f"(x)); return r;
}
__device__ __forceinline__ void mma8(float* c, const uint32_t* a, const uint32_t* b) {
    asm volatile("mma.sync.aligned.m16n8k8.row.col.f32.tf32.tf32.f32 "
                 "{%0,%1,%2,%3},{%4,%5,%6,%7},{%8,%9},{%0,%1,%2,%3};"
                 : "+f"(c[0]), "+f"(c[1]), "+f"(c[2]), "+f"(c[3])
                 : "r"(a[0]), "r"(a[1]), "r"(a[2]), "r"(a[3]),
                   "r"(b[0]), "r"(b[1]));
}
__device__ __forceinline__ uint32_t smaddr(const void* p) {
    return (uint32_t)__cvta_generic_to_shared(p);
}
__device__ __forceinline__ void cpa16(uint32_t dst, const void* src) {
    asm volatile("cp.async.cg.shared.global [%0], [%1], 16;" :: "r"(dst), "l"(src));
}

// ---------------- tf32 GEMM: C[M,N] = A[M,K] * B[N,K]^T + bias ---------------
// block 128x128, k-tile 32, 256 threads (8 warps, each 32x64), cp.async 2-buf.
// blockIdx.z selects one of up to 3 (B, bias, C) triples (fused QKV).
#define GBK 32
#define LDT 36
#define GBUF (128 * LDT)

__device__ __forceinline__ void gemm_body(
        const float* __restrict__ A, const float* __restrict__ B,
        const float* __restrict__ bias, float* __restrict__ C,
        int M, int N, int K) {
    extern __shared__ float gsm[];
    float* sA = gsm;
    float* sB = gsm + 2 * GBUF;
    const uint32_t aAddr = smaddr(sA);
    const uint32_t bAddr = smaddr(sB);

    const int tid = threadIdx.x;
    const int wid = tid >> 5, lane = tid & 31;
    const int wm = wid & 3, wn = wid >> 2;
    const int rowBase = blockIdx.y * 128, colBase = blockIdx.x * 128;

    int lrow[4], lcol[4];
    #pragma unroll
    for (int i = 0; i < 4; i++) {
        int idx = tid + 256 * i;
        lrow[i] = idx >> 3;
        lcol[i] = (idx & 7) * 4;
    }

    float acc[2][8][4];
    #pragma unroll
    for (int i = 0; i < 2; i++)
        #pragma unroll
        for (int j = 0; j < 8; j++)
            #pragma unroll
            for (int t = 0; t < 4; t++) acc[i][j][t] = 0.f;

    #pragma unroll
    for (int i = 0; i < 4; i++) {
        cpa16(aAddr + (uint32_t)(lrow[i] * LDT + lcol[i]) * 4,
              A + (size_t)(rowBase + lrow[i]) * K + lcol[i]);
        cpa16(bAddr + (uint32_t)(lrow[i] * LDT + lcol[i]) * 4,
              B + (size_t)(colBase + lrow[i]) * K + lcol[i]);
    }
    asm volatile("cp.async.commit_group;");

    int buf = 0;
    for (int k0 = 0; k0 < K; k0 += GBK) {
        if (k0 + GBK < K) {
            uint32_t off = (uint32_t)((buf ^ 1) * GBUF) * 4;
            #pragma unroll
            for (int i = 0; i < 4; i++) {
                cpa16(aAddr + off + (uint32_t)(lrow[i] * LDT + lcol[i]) * 4,
                      A + (size_t)(rowBase + lrow[i]) * K + k0 + GBK + lcol[i]);
                cpa16(bAddr + off + (uint32_t)(lrow[i] * LDT + lcol[i]) * 4,
                      B + (size_t)(colBase + lrow[i]) * K + k0 + GBK + lcol[i]);
            }
            asm volatile("cp.async.commit_group;");
            asm volatile("cp.async.wait_group 1;");
        } else {
            asm volatile("cp.async.wait_group 0;");
        }
        __syncthreads();

        const float* bAp = sA + buf * GBUF;
        const float* bBp = sB + buf * GBUF;
        #pragma unroll
        for (int kk = 0; kk < GBK; kk += 8) {
            uint32_t af[2][4], bf[8][2];
            #pragma unroll
            for (int i = 0; i < 2; i++) {
                const float* p = bAp + (wm * 32 + i * 16 + (lane >> 2)) * LDT
                                 + kk + (lane & 3);
                af[i][0] = f2tf(p[0]);
                af[i][1] = f2tf(p[8 * LDT]);
                af[i][2] = f2tf(p[4]);
                af[i][3] = f2tf(p[8 * LDT + 4]);
            }
            #pragma unroll
            for (int j = 0; j < 8; j++) {
                const float* p = bBp + (wn * 64 + j * 8 + (lane >> 2)) * LDT
                                 + kk + (lane & 3);
                bf[j][0] = f2tf(p[0]);
                bf[j][1] = f2tf(p[4]);
            }
            #pragma unroll
            for (int i = 0; i < 2; i++)
                #pragma unroll
                for (int j = 0; j < 8; j++)
                    mma8(acc[i][j], af[i], bf[j]);
        }
        __syncthreads();
        buf ^= 1;
    }

    #pragma unroll
    for (int i = 0; i < 2; i++) {
        int r0 = rowBase + wm * 32 + i * 16 + (lane >> 2);
        #pragma unroll
        for (int j = 0; j < 8; j++) {
            int cl = colBase + wn * 64 + j * 8 + 2 * (lane & 3);
            float2 bv = *(const float2*)(bias + cl);
            float2 lo = make_float2(acc[i][j][0] + bv.x, acc[i][j][1] + bv.y);
            float2 hi = make_float2(acc[i][j][2] + bv.x, acc[i][j][3] + bv.y);
            *(float2*)(C + (size_t)r0 * N + cl) = lo;
            *(float2*)(C + (size_t)(r0 + 8) * N + cl) = hi;
        }
    }
}

__global__ __launch_bounds__(256) void gemm_qkv(
        const float* __restrict__ A,
        const float* __restrict__ B0, const float* __restrict__ b0, float* C0,
        const float* __restrict__ B1, const float* __restrict__ b1, float* C1,
        const float* __restrict__ B2, const float* __restrict__ b2, float* C2) {
    const float* B = (blockIdx.z == 0) ? B0 : (blockIdx.z == 1) ? B1 : B2;
    const float* b = (blockIdx.z == 0) ? b0 : (blockIdx.z == 1) ? b1 : b2;
    float*       C = (blockIdx.z == 0) ? C0 : (blockIdx.z == 1) ? C1 : C2;
    gemm_body(A, B, b, C, SEQ, DIM, DIM);
}

__global__ __launch_bounds__(256) void gemm_single(
        const float* __restrict__ A, const float* __restrict__ B,
        const float* __restrict__ bias, float* __restrict__ C) {
    gemm_body(A, B, bias, C, SEQ, DIM, DIM);
}

// ---------------- RoPE cos/sin table -----------------------------------------
__global__ void build_cs_kernel(const float* __restrict__ fc,
                                const float* __restrict__ fs) {
    int s = blockIdx.x;
    int c = threadIdx.x;
    int fi, hi, wi;
    if (s < 3840) { fi = s >> 8; hi = (s >> 4) & 15; wi = s & 15; }
    else          { fi = 1023; int r = s - 3840; hi = r >> 4; wi = r & 15; }
    int row;
    if (c < 22)      row = fi;
    else if (c < 43) row = hi;
    else             row = wi;
    g_cos[s * CC + c] = fc[row * CC + c];
    g_sin[s * CC + c] = fs[row * CC + c];
}

// ---------------- fused RMSNorm + RoPE (in place) -----------------------------
__global__ void rmsnorm_rope_kernel(float* __restrict__ X,
                                    const float* __restrict__ w) {
    int s = blockIdx.x;
    int tid = threadIdx.x;
    int d0 = tid * 4;
    float4 v = *(const float4*)&X[(size_t)s * DIM + d0];
    float ss = v.x * v.x + v.y * v.y + v.z * v.z + v.w * v.w;
    #pragma unroll
    for (int o = 16; o > 0; o >>= 1) ss += __shfl_xor_sync(0xffffffffu, ss, o);
    __shared__ float red[12];
    __shared__ float scale_sh;
    int warp = tid >> 5, lane = tid & 31;
    if (lane == 0) red[warp] = ss;
    __syncthreads();
    if (tid == 0) {
        float t = 0.f;
        #pragma unroll
        for (int i = 0; i < 12; i++) t += red[i];
        scale_sh = rsqrtf(t / (float)DIM + 1e-6f);
    }
    __syncthreads();
    float sc = scale_sh;
    float4 wv = *(const float4*)&w[d0];
    float x0 = v.x * sc * wv.x, x1 = v.y * sc * wv.y;
    float x2 = v.z * sc * wv.z, x3 = v.w * sc * wv.w;
    int c = (d0 & 127) >> 1;
    float c0 = g_cos[s * CC + c],     s0 = g_sin[s * CC + c];
    float c1 = g_cos[s * CC + c + 1], s1 = g_sin[s * CC + c + 1];
    float4 o;
    o.x = x0 * c0 - x1 * s0;
    o.y = x0 * s0 + x1 * c0;
    o.z = x2 * c1 - x3 * s1;
    o.w = x2 * s1 + x3 * c1;
    *(float4*)&X[(size_t)s * DIM + d0] = o;
}

// ---------------- flash attention, tf32 + cp.async double-buffered KV --------
// grid (32 q-tiles, 12 heads), 256 thr (8 warps, each m16). BQ=128, BK=64.
// smem (floats): sK[2][64*LK] | sV[2][64*LV] | sP[128*LP]
// Q staged raw over the KV region (consumed into registers before cp.async).
#define LK 132   // 132 % 32 == 4 -> conflict-free K frag loads
#define LV 136   // 136 % 32 == 8 -> conflict-free V frag loads
#define LP 72    //  72 % 32 == 8 -> conflict-free P frag loads
#define KVW (2 * 64 * LK + 2 * 64 * LV)   // 34304 words

__global__ __launch_bounds__(256, 1) void attn_tf32(
        const float* __restrict__ Q, const float* __restrict__ K,
        const float* __restrict__ V, float* __restrict__ O) {
    extern __shared__ float smf[];
    float* sKb[2] = { smf, smf + 64 * LK };
    float* sVb[2] = { smf + 2 * 64 * LK, smf + 2 * 64 * LK + 64 * LV };
    uint32_t* sP = (uint32_t*)(smf + KVW);
    float* sQ = smf;                      // staging, aliases KV ring

    const int h = blockIdx.y;
    const int q0 = blockIdx.x * 128;
    const int tid = threadIdx.x, wid = tid >> 5, lane = tid & 31;
    const int lq = lane >> 2, lr = lane & 3;

    const uint32_t kA[2] = { smaddr(sKb[0]), smaddr(sKb[1]) };
    const uint32_t vA[2] = { smaddr(sVb[0]), smaddr(sVb[1]) };

    // stage raw Q, hoist pre-scaled tf32 fragments, then release region
    for (int i = tid; i < 128 * 32; i += 256) {
        int r = i >> 5, c4 = (i & 31) * 4;
        *(float4*)(sQ + r * LK + c4) =
            *(const float4*)(Q + (size_t)(q0 + r) * DIM + h * HD + c4);
    }
    __syncthreads();
    uint32_t qf[16][4];
    {
        const float* p0 = sQ + (wid * 16 + lq) * LK + lr;
        #pragma unroll
        for (int ks = 0; ks < 16; ks++) {
            const float* p = p0 + ks * 8;
            qf[ks][0] = f2tf(p[0] * ATTN_SCALE);
            qf[ks][1] = f2tf(p[8 * LK] * ATTN_SCALE);
            qf[ks][2] = f2tf(p[4] * ATTN_SCALE);
            qf[ks][3] = f2tf(p[8 * LK + 4] * ATTN_SCALE);
        }
    }
    __syncthreads();

    // loader pattern: 8 float4 per matrix per thread per tile
    int krow[8], kcol[8];
    #pragma unroll
    for (int i = 0; i < 8; i++) {
        int idx = tid + 256 * i;
        krow[i] = idx >> 5;
        kcol[i] = (idx & 31) * 4;
    }
    // prologue: tile 0 -> buf 0
    #pragma unroll
    for (int i = 0; i < 8; i++) {
        const float* ks_ = K + (size_t)krow[i] * DIM + h * HD + kcol[i];
        const float* vs_ = V + (size_t)krow[i] * DIM + h * HD + kcol[i];
        cpa16(kA[0] + (uint32_t)(krow[i] * LK + kcol[i]) * 4, ks_);
        cpa16(vA[0] + (uint32_t)(krow[i] * LV + kcol[i]) * 4, vs_);
    }
    asm volatile("cp.async.commit_group;");

    float oacc[16][4];
    #pragma unroll
    for (int j = 0; j < 16; j++)
        #pragma unroll
        for (int t = 0; t < 4; t++) oacc[j][t] = 0.f;
    float m0 = -1e30f, m1 = -1e30f, l0 = 0.f, l1 = 0.f;

    int buf = 0;
    for (int kt = 0; kt < SEQ; kt += 64) {
        if (kt + 64 < SEQ) {
            int nb = buf ^ 1;
            #pragma unroll
            for (int i = 0; i < 8; i++) {
                const float* ks_ = K + (size_t)(kt + 64 + krow[i]) * DIM + h * HD + kcol[i];
                const float* vs_ = V + (size_t)(kt + 64 + krow[i]) * DIM + h * HD + kcol[i];
                cpa16(kA[nb] + (uint32_t)(krow[i] * LK + kcol[i]) * 4, ks_);
                cpa16(vA[nb] + (uint32_t)(krow[i] * LV + kcol[i]) * 4, vs_);
            }
            asm volatile("cp.async.commit_group;");
            asm volatile("cp.async.wait_group 1;");
        } else {
            asm volatile("cp.async.wait_group 0;");
        }
        __syncthreads();

        const float* sKc = sKb[buf];
        const float* sVc = sVb[buf];

        // S = Q K^T : per warp m16 x n64, k=128 (cvt on the fly)
        float sf[8][4];
        #pragma unroll
        for (int j = 0; j < 8; j++)
            #pragma unroll
            for (int t = 0; t < 4; t++) sf[j][t] = 0.f;
        #pragma unroll
        for (int ks = 0; ks < 16; ks++) {
            uint32_t bf[8][2];
            #pragma unroll
            for (int j = 0; j < 8; j++) {
                const float* p = sKc + (j * 8 + lq) * LK + ks * 8 + lr;
                bf[j][0] = f2tf(p[0]);
                bf[j][1] = f2tf(p[4]);
            }
            #pragma unroll
            for (int j = 0; j < 8; j++) mma8(sf[j], qf[ks], bf[j]);
        }

        // in-register online softmax
        float mx0 = -1e30f, mx1 = -1e30f;
        #pragma unroll
        for (int j = 0; j < 8; j++) {
            mx0 = fmaxf(mx0, fmaxf(sf[j][0], sf[j][1]));
            mx1 = fmaxf(mx1, fmaxf(sf[j][2], sf[j][3]));
        }
        mx0 = fmaxf(mx0, __shfl_xor_sync(0xffffffffu, mx0, 1));
        mx0 = fmaxf(mx0, __shfl_xor_sync(0xffffffffu, mx0, 2));
        mx1 = fmaxf(mx1, __shfl_xor_sync(0xffffffffu, mx1, 1));
        mx1 = fmaxf(mx1, __shfl_xor_sync(0xffffffffu, mx1, 2));
        float nm0 = fmaxf(m0, mx0), nm1 = fmaxf(m1, mx1);
        float c0 = __expf(m0 - nm0), c1 = __expf(m1 - nm1);
        m0 = nm0; m1 = nm1; l0 *= c0; l1 *= c1;
        #pragma unroll
        for (int j = 0; j < 16; j++) {
            oacc[j][0] *= c0; oacc[j][1] *= c0;
            oacc[j][2] *= c1; oacc[j][3] *= c1;
        }
        float ls0 = 0.f, ls1 = 0.f;
        {
            int r = wid * 16 + lq;
            #pragma unroll
            for (int j = 0; j < 8; j++) {
                float p0 = __expf(sf[j][0] - nm0);
                float p1 = __expf(sf[j][1] - nm0);
                float p2 = __expf(sf[j][2] - nm1);
                float p3 = __expf(sf[j][3] - nm1);
                ls0 += p0 + p1; ls1 += p2 + p3;
                int cb = j * 8 + 2 * lr;
                sP[r * LP + cb]           = f2tf(p0);
                sP[r * LP + cb + 1]       = f2tf(p1);
                sP[(r + 8) * LP + cb]     = f2tf(p2);
                sP[(r + 8) * LP + cb + 1] = f2tf(p3);
            }
        }
        ls0 += __shfl_xor_sync(0xffffffffu, ls0, 1);
        ls0 += __shfl_xor_sync(0xffffffffu, ls0, 2);
        ls1 += __shfl_xor_sync(0xffffffffu, ls1, 1);
        ls1 += __shfl_xor_sync(0xffffffffu, ls1, 2);
        l0 += ls0; l1 += ls1;
        __syncthreads();

        // O += P V : per warp m16 x n128, k=64
        #pragma unroll
        for (int ks = 0; ks < 8; ks++) {
            uint32_t af[4];
            const uint32_t* pp = sP + (wid * 16 + lq) * LP + ks * 8 + lr;
            af[0] = pp[0];
            af[1] = pp[8 * LP];
            af[2] = pp[4];
            af[3] = pp[8 * LP + 4];
            #pragma unroll
            for (int j = 0; j < 16; j++) {
                uint32_t bf[2];
                const float* vp = sVc + (ks * 8 + lr) * LV + j * 8 + lq;
                bf[0] = f2tf(vp[0]);
                bf[1] = f2tf(vp[4 * LV]);
                mma8(oacc[j], af, bf);
            }
        }
        __syncthreads();   // all warps done with buf before it is refilled
        buf ^= 1;
    }

    float inv0 = 1.f / l0, inv1 = 1.f / l1;
    int r = q0 + wid * 16 + lq;
    #pragma unroll
    for (int j = 0; j < 16; j++) {
        int c = h * HD + j * 8 + 2 * lr;
        float2 lo = make_float2(oacc[j][0] * inv0, oacc[j][1] * inv0);
        float2 hi = make_float2(oacc[j][2] * inv1, oacc[j][3] * inv1);
        *(float2*)(O + (size_t)r * DIM + c) = lo;
        *(float2*)(O + (size_t)(r + 8) * DIM + c) = hi;
    }
}

// ---------------------------------------------------------------------------
extern "C" void kernel_launch(void* const* d_in, const int* in_sizes, int n_in,
                              void* d_out, int out_size) {
    const float* x    = (const float*)d_in[0];
    const float* Wq   = (const float*)d_in[1];
    const float* bq   = (const float*)d_in[2];
    const float* Wk   = (const float*)d_in[3];
    const float* bk   = (const float*)d_in[4];
    const float* Wv   = (const float*)d_in[5];
    const float* bv   = (const float*)d_in[6];
    const float* Wo   = (const float*)d_in[7];
    const float* bo   = (const float*)d_in[8];
    const float* nqw  = (const float*)d_in[9];
    const float* nkw  = (const float*)d_in[10];
    const float* fcos = (const float*)d_in[11];
    const float* fsin = (const float*)d_in[12];
    float* out = (float*)d_out;

    float *pq, *pk, *pv, *pa;
    cudaGetSymbolAddress((void**)&pq, g_q);
    cudaGetSymbolAddress((void**)&pk, g_k);
    cudaGetSymbolAddress((void**)&pv, g_v);
    cudaGetSymbolAddress((void**)&pa, g_attn);

    const int gemm_smem = 4 * GBUF * 4;                       // 73728
    cudaFuncSetAttribute(gemm_qkv,
                         cudaFuncAttributeMaxDynamicSharedMemorySize, gemm_smem);
    cudaFuncSetAttribute(gemm_single,
                         cudaFuncAttributeMaxDynamicSharedMemorySize, gemm_smem);
    const int attn_smem = (KVW + 128 * LP) * 4;               // 174080
    cudaFuncSetAttribute(attn_tf32,
                         cudaFuncAttributeMaxDynamicSharedMemorySize, attn_smem);

    gemm_qkv<<<dim3(DIM / 128, SEQ / 128, 3), 256, gemm_smem>>>(
        x, Wq, bq, pq, Wk, bk, pk, Wv, bv, pv);

    build_cs_kernel<<<SEQ, CC>>>(fcos, fsin);
    rmsnorm_rope_kernel<<<SEQ, 384>>>(pq, nqw);
    rmsnorm_rope_kernel<<<SEQ, 384>>>(pk, nkw);

    attn_tf32<<<dim3(SEQ / 128, HEADS), 256, attn_smem>>>(pq, pk, pv, pa);

    gemm_single<<<dim3(DIM / 128, SEQ / 128), 256, gemm_smem>>>(pa, Wo, bo, out);
}

// round 6
// speedup vs baseline: 1.1543x; 1.1543x over previous
#include <cuda_runtime.h>
#include <math.h>
#include <stdint.h>

#define DIM   1536
#define SEQ   4096
#define HEADS 12
#define HD    128
#define CC    64
#define ATTN_SCALE 0.08838834764831845f   // 1/sqrt(128)

// ---------------- scratch ----------------------------------------------------
__device__ float g_q[SEQ * DIM];
__device__ float g_k[SEQ * DIM];
__device__ float g_v[SEQ * DIM];
__device__ float g_attn[SEQ * DIM];
__device__ float g_cos[SEQ * CC];
__device__ float g_sin[SEQ * CC];

// ---------------- helpers ----------------------------------------------------
__device__ __forceinline__ uint32_t f2tf(float x) {
    uint32_t r; asm("cvt.rna.tf32.f32 %0, %1;" : "=r"(r) : "f"(x)); return r;
}
__device__ __forceinline__ void mma8(float* c, const uint32_t* a, const uint32_t* b) {
    asm volatile("mma.sync.aligned.m16n8k8.row.col.f32.tf32.tf32.f32 "
                 "{%0,%1,%2,%3},{%4,%5,%6,%7},{%8,%9},{%0,%1,%2,%3};"
                 : "+f"(c[0]), "+f"(c[1]), "+f"(c[2]), "+f"(c[3])
                 : "r"(a[0]), "r"(a[1]), "r"(a[2]), "r"(a[3]),
                   "r"(b[0]), "r"(b[1]));
}
__device__ __forceinline__ uint32_t smaddr(const void* p) {
    return (uint32_t)__cvta_generic_to_shared(p);
}
__device__ __forceinline__ void cpa16(uint32_t dst, const void* src) {
    asm volatile("cp.async.cg.shared.global [%0], [%1], 16;" :: "r"(dst), "l"(src));
}

// ---------------- tf32 GEMM: C[M,N] = A[M,K] * B[N,K]^T + bias ---------------
// block 128x128, k-tile 32, 256 threads (8 warps, each 32x64), cp.async 2-buf.
#define GBK 32
#define LDT 36
#define GBUF (128 * LDT)

__device__ __forceinline__ void gemm_body(
        const float* __restrict__ A, const float* __restrict__ B,
        const float* __restrict__ bias, float* __restrict__ C,
        int M, int N, int K) {
    extern __shared__ float gsm[];
    float* sA = gsm;
    float* sB = gsm + 2 * GBUF;
    const uint32_t aAddr = smaddr(sA);
    const uint32_t bAddr = smaddr(sB);

    const int tid = threadIdx.x;
    const int wid = tid >> 5, lane = tid & 31;
    const int wm = wid & 3, wn = wid >> 2;
    const int rowBase = blockIdx.y * 128, colBase = blockIdx.x * 128;

    int lrow[4], lcol[4];
    #pragma unroll
    for (int i = 0; i < 4; i++) {
        int idx = tid + 256 * i;
        lrow[i] = idx >> 3;
        lcol[i] = (idx & 7) * 4;
    }

    float acc[2][8][4];
    #pragma unroll
    for (int i = 0; i < 2; i++)
        #pragma unroll
        for (int j = 0; j < 8; j++)
            #pragma unroll
            for (int t = 0; t < 4; t++) acc[i][j][t] = 0.f;

    #pragma unroll
    for (int i = 0; i < 4; i++) {
        cpa16(aAddr + (uint32_t)(lrow[i] * LDT + lcol[i]) * 4,
              A + (size_t)(rowBase + lrow[i]) * K + lcol[i]);
        cpa16(bAddr + (uint32_t)(lrow[i] * LDT + lcol[i]) * 4,
              B + (size_t)(colBase + lrow[i]) * K + lcol[i]);
    }
    asm volatile("cp.async.commit_group;");

    int buf = 0;
    for (int k0 = 0; k0 < K; k0 += GBK) {
        if (k0 + GBK < K) {
            uint32_t off = (uint32_t)((buf ^ 1) * GBUF) * 4;
            #pragma unroll
            for (int i = 0; i < 4; i++) {
                cpa16(aAddr + off + (uint32_t)(lrow[i] * LDT + lcol[i]) * 4,
                      A + (size_t)(rowBase + lrow[i]) * K + k0 + GBK + lcol[i]);
                cpa16(bAddr + off + (uint32_t)(lrow[i] * LDT + lcol[i]) * 4,
                      B + (size_t)(colBase + lrow[i]) * K + k0 + GBK + lcol[i]);
            }
            asm volatile("cp.async.commit_group;");
            asm volatile("cp.async.wait_group 1;");
        } else {
            asm volatile("cp.async.wait_group 0;");
        }
        __syncthreads();

        const float* bAp = sA + buf * GBUF;
        const float* bBp = sB + buf * GBUF;
        #pragma unroll
        for (int kk = 0; kk < GBK; kk += 8) {
            uint32_t af[2][4], bf[8][2];
            #pragma unroll
            for (int i = 0; i < 2; i++) {
                const float* p = bAp + (wm * 32 + i * 16 + (lane >> 2)) * LDT
                                 + kk + (lane & 3);
                af[i][0] = f2tf(p[0]);
                af[i][1] = f2tf(p[8 * LDT]);
                af[i][2] = f2tf(p[4]);
                af[i][3] = f2tf(p[8 * LDT + 4]);
            }
            #pragma unroll
            for (int j = 0; j < 8; j++) {
                const float* p = bBp + (wn * 64 + j * 8 + (lane >> 2)) * LDT
                                 + kk + (lane & 3);
                bf[j][0] = f2tf(p[0]);
                bf[j][1] = f2tf(p[4]);
            }
            #pragma unroll
            for (int i = 0; i < 2; i++)
                #pragma unroll
                for (int j = 0; j < 8; j++)
                    mma8(acc[i][j], af[i], bf[j]);
        }
        __syncthreads();
        buf ^= 1;
    }

    #pragma unroll
    for (int i = 0; i < 2; i++) {
        int r0 = rowBase + wm * 32 + i * 16 + (lane >> 2);
        #pragma unroll
        for (int j = 0; j < 8; j++) {
            int cl = colBase + wn * 64 + j * 8 + 2 * (lane & 3);
            float2 bv = *(const float2*)(bias + cl);
            float2 lo = make_float2(acc[i][j][0] + bv.x, acc[i][j][1] + bv.y);
            float2 hi = make_float2(acc[i][j][2] + bv.x, acc[i][j][3] + bv.y);
            *(float2*)(C + (size_t)r0 * N + cl) = lo;
            *(float2*)(C + (size_t)(r0 + 8) * N + cl) = hi;
        }
    }
}

__global__ __launch_bounds__(256) void gemm_qkv(
        const float* __restrict__ A,
        const float* __restrict__ B0, const float* __restrict__ b0, float* C0,
        const float* __restrict__ B1, const float* __restrict__ b1, float* C1,
        const float* __restrict__ B2, const float* __restrict__ b2, float* C2) {
    const float* B = (blockIdx.z == 0) ? B0 : (blockIdx.z == 1) ? B1 : B2;
    const float* b = (blockIdx.z == 0) ? b0 : (blockIdx.z == 1) ? b1 : b2;
    float*       C = (blockIdx.z == 0) ? C0 : (blockIdx.z == 1) ? C1 : C2;
    gemm_body(A, B, b, C, SEQ, DIM, DIM);
}

__global__ __launch_bounds__(256) void gemm_single(
        const float* __restrict__ A, const float* __restrict__ B,
        const float* __restrict__ bias, float* __restrict__ C) {
    gemm_body(A, B, bias, C, SEQ, DIM, DIM);
}

// ---------------- RoPE cos/sin table -----------------------------------------
__global__ void build_cs_kernel(const float* __restrict__ fc,
                                const float* __restrict__ fs) {
    int s = blockIdx.x;
    int c = threadIdx.x;
    int fi, hi, wi;
    if (s < 3840) { fi = s >> 8; hi = (s >> 4) & 15; wi = s & 15; }
    else          { fi = 1023; int r = s - 3840; hi = r >> 4; wi = r & 15; }
    int row;
    if (c < 22)      row = fi;
    else if (c < 43) row = hi;
    else             row = wi;
    g_cos[s * CC + c] = fc[row * CC + c];
    g_sin[s * CC + c] = fs[row * CC + c];
}

// ---------------- fused RMSNorm + RoPE (in place) -----------------------------
__global__ void rmsnorm_rope_kernel(float* __restrict__ X,
                                    const float* __restrict__ w) {
    int s = blockIdx.x;
    int tid = threadIdx.x;
    int d0 = tid * 4;
    float4 v = *(const float4*)&X[(size_t)s * DIM + d0];
    float ss = v.x * v.x + v.y * v.y + v.z * v.z + v.w * v.w;
    #pragma unroll
    for (int o = 16; o > 0; o >>= 1) ss += __shfl_xor_sync(0xffffffffu, ss, o);
    __shared__ float red[12];
    __shared__ float scale_sh;
    int warp = tid >> 5, lane = tid & 31;
    if (lane == 0) red[warp] = ss;
    __syncthreads();
    if (tid == 0) {
        float t = 0.f;
        #pragma unroll
        for (int i = 0; i < 12; i++) t += red[i];
        scale_sh = rsqrtf(t / (float)DIM + 1e-6f);
    }
    __syncthreads();
    float sc = scale_sh;
    float4 wv = *(const float4*)&w[d0];
    float x0 = v.x * sc * wv.x, x1 = v.y * sc * wv.y;
    float x2 = v.z * sc * wv.z, x3 = v.w * sc * wv.w;
    int c = (d0 & 127) >> 1;
    float c0 = g_cos[s * CC + c],     s0 = g_sin[s * CC + c];
    float c1 = g_cos[s * CC + c + 1], s1 = g_sin[s * CC + c + 1];
    float4 o;
    o.x = x0 * c0 - x1 * s0;
    o.y = x0 * s0 + x1 * c0;
    o.z = x2 * c1 - x3 * s1;
    o.w = x2 * s1 + x3 * c1;
    *(float4*)&X[(size_t)s * DIM + d0] = o;
}

// ---------------- flash attention, tf32, 2 CTAs/SM ---------------------------
// grid (64 q-tiles, 12 heads), 128 thr (4 warps, each m16). BQ=64, BK=64.
// smem (words): sK[64][LK] | sV[64][LV] | sP[64][LP]  = 21760 w = 87040 B
// K/V converted to tf32 once at fill; sP per-warp-private (syncwarp only).
#define LK 132   // 132 % 32 == 4 -> conflict-free K frag loads
#define LV 136   // 136 % 32 == 8 -> conflict-free V frag loads
#define LP 72    //  72 % 32 == 8 -> conflict-free P frag loads

__global__ __launch_bounds__(128, 2) void attn_tf32(
        const float* __restrict__ Q, const float* __restrict__ K,
        const float* __restrict__ V, float* __restrict__ O) {
    extern __shared__ uint32_t smu[];
    uint32_t* sK = smu;                    // [64][LK]
    uint32_t* sV = sK + 64 * LK;           // [64][LV]
    uint32_t* sP = sV + 64 * LV;           // [64][LP]

    const int h = blockIdx.y;
    const int q0 = blockIdx.x * 64;
    const int tid = threadIdx.x, wid = tid >> 5, lane = tid & 31;
    const int lq = lane >> 2, lr = lane & 3;

    // Q fragments straight from global (once per CTA), pre-scaled tf32
    uint32_t qf[16][4];
    {
        const float* qp = Q + (size_t)(q0 + wid * 16 + lq) * DIM + h * HD + lr;
        #pragma unroll
        for (int ks = 0; ks < 16; ks++) {
            const float* p = qp + ks * 8;
            qf[ks][0] = f2tf(p[0] * ATTN_SCALE);
            qf[ks][1] = f2tf(p[8 * DIM] * ATTN_SCALE);
            qf[ks][2] = f2tf(p[4] * ATTN_SCALE);
            qf[ks][3] = f2tf(p[8 * DIM + 4] * ATTN_SCALE);
        }
    }

    float oacc[16][4];
    #pragma unroll
    for (int j = 0; j < 16; j++)
        #pragma unroll
        for (int t = 0; t < 4; t++) oacc[j][t] = 0.f;
    float m0 = -1e30f, m1 = -1e30f, l0 = 0.f, l1 = 0.f;

    for (int kt = 0; kt < SEQ; kt += 64) {
        __syncthreads();   // previous tile's consumers done with sK/sV
        // fill sK, sV (convert once here)
        #pragma unroll
        for (int i = 0; i < 16; i++) {
            int idx = tid + 128 * i;
            int r = idx >> 5, c4 = (idx & 31) * 4;
            float4 kv = *(const float4*)(K + (size_t)(kt + r) * DIM + h * HD + c4);
            float4 vv = *(const float4*)(V + (size_t)(kt + r) * DIM + h * HD + c4);
            uint4 dk = make_uint4(f2tf(kv.x), f2tf(kv.y), f2tf(kv.z), f2tf(kv.w));
            uint4 dv = make_uint4(f2tf(vv.x), f2tf(vv.y), f2tf(vv.z), f2tf(vv.w));
            *(uint4*)(sK + r * LK + c4) = dk;
            *(uint4*)(sV + r * LV + c4) = dv;
        }
        __syncthreads();

        // S = Q K^T : per warp m16 x n64, k=128
        float sf[8][4];
        #pragma unroll
        for (int j = 0; j < 8; j++)
            #pragma unroll
            for (int t = 0; t < 4; t++) sf[j][t] = 0.f;
        #pragma unroll
        for (int ks = 0; ks < 16; ks++) {
            uint32_t bf[8][2];
            #pragma unroll
            for (int j = 0; j < 8; j++) {
                const uint32_t* p = sK + (j * 8 + lq) * LK + ks * 8 + lr;
                bf[j][0] = p[0];
                bf[j][1] = p[4];
            }
            #pragma unroll
            for (int j = 0; j < 8; j++) mma8(sf[j], qf[ks], bf[j]);
        }

        // in-register online softmax (rows lq and lq+8 of this warp's m16)
        float mx0 = -1e30f, mx1 = -1e30f;
        #pragma unroll
        for (int j = 0; j < 8; j++) {
            mx0 = fmaxf(mx0, fmaxf(sf[j][0], sf[j][1]));
            mx1 = fmaxf(mx1, fmaxf(sf[j][2], sf[j][3]));
        }
        mx0 = fmaxf(mx0, __shfl_xor_sync(0xffffffffu, mx0, 1));
        mx0 = fmaxf(mx0, __shfl_xor_sync(0xffffffffu, mx0, 2));
        mx1 = fmaxf(mx1, __shfl_xor_sync(0xffffffffu, mx1, 1));
        mx1 = fmaxf(mx1, __shfl_xor_sync(0xffffffffu, mx1, 2));
        float nm0 = fmaxf(m0, mx0), nm1 = fmaxf(m1, mx1);
        float c0 = __expf(m0 - nm0), c1 = __expf(m1 - nm1);
        m0 = nm0; m1 = nm1; l0 *= c0; l1 *= c1;
        #pragma unroll
        for (int j = 0; j < 16; j++) {
            oacc[j][0] *= c0; oacc[j][1] *= c0;
            oacc[j][2] *= c1; oacc[j][3] *= c1;
        }
        float ls0 = 0.f, ls1 = 0.f;
        {
            int r = wid * 16 + lq;
            #pragma unroll
            for (int j = 0; j < 8; j++) {
                float p0 = __expf(sf[j][0] - nm0);
                float p1 = __expf(sf[j][1] - nm0);
                float p2 = __expf(sf[j][2] - nm1);
                float p3 = __expf(sf[j][3] - nm1);
                ls0 += p0 + p1; ls1 += p2 + p3;
                int cb = j * 8 + 2 * lr;
                sP[r * LP + cb]           = f2tf(p0);
                sP[r * LP + cb + 1]       = f2tf(p1);
                sP[(r + 8) * LP + cb]     = f2tf(p2);
                sP[(r + 8) * LP + cb + 1] = f2tf(p3);
            }
        }
        ls0 += __shfl_xor_sync(0xffffffffu, ls0, 1);
        ls0 += __shfl_xor_sync(0xffffffffu, ls0, 2);
        ls1 += __shfl_xor_sync(0xffffffffu, ls1, 1);
        ls1 += __shfl_xor_sync(0xffffffffu, ls1, 2);
        l0 += ls0; l1 += ls1;
        __syncwarp();   // sP rows are warp-private; warp-level fence suffices

        // O += P V : per warp m16 x n128, k=64
        #pragma unroll
        for (int ks = 0; ks < 8; ks++) {
            uint32_t af[4];
            const uint32_t* pp = sP + (wid * 16 + lq) * LP + ks * 8 + lr;
            af[0] = pp[0];
            af[1] = pp[8 * LP];
            af[2] = pp[4];
            af[3] = pp[8 * LP + 4];
            #pragma unroll
            for (int j = 0; j < 16; j++) {
                uint32_t bf[2];
                const uint32_t* vp = sV + (ks * 8 + lr) * LV + j * 8 + lq;
                bf[0] = vp[0];
                bf[1] = vp[4 * LV];
                mma8(oacc[j], af, bf);
            }
        }
    }

    float inv0 = 1.f / l0, inv1 = 1.f / l1;
    int r = q0 + wid * 16 + lq;
    #pragma unroll
    for (int j = 0; j < 16; j++) {
        int c = h * HD + j * 8 + 2 * lr;
        float2 lo = make_float2(oacc[j][0] * inv0, oacc[j][1] * inv0);
        float2 hi = make_float2(oacc[j][2] * inv1, oacc[j][3] * inv1);
        *(float2*)(O + (size_t)r * DIM + c) = lo;
        *(float2*)(O + (size_t)(r + 8) * DIM + c) = hi;
    }
}

// ---------------------------------------------------------------------------
extern "C" void kernel_launch(void* const* d_in, const int* in_sizes, int n_in,
                              void* d_out, int out_size) {
    const float* x    = (const float*)d_in[0];
    const float* Wq   = (const float*)d_in[1];
    const float* bq   = (const float*)d_in[2];
    const float* Wk   = (const float*)d_in[3];
    const float* bk   = (const float*)d_in[4];
    const float* Wv   = (const float*)d_in[5];
    const float* bv   = (const float*)d_in[6];
    const float* Wo   = (const float*)d_in[7];
    const float* bo   = (const float*)d_in[8];
    const float* nqw  = (const float*)d_in[9];
    const float* nkw  = (const float*)d_in[10];
    const float* fcos = (const float*)d_in[11];
    const float* fsin = (const float*)d_in[12];
    float* out = (float*)d_out;

    float *pq, *pk, *pv, *pa;
    cudaGetSymbolAddress((void**)&pq, g_q);
    cudaGetSymbolAddress((void**)&pk, g_k);
    cudaGetSymbolAddress((void**)&pv, g_v);
    cudaGetSymbolAddress((void**)&pa, g_attn);

    const int gemm_smem = 4 * GBUF * 4;                       // 73728
    cudaFuncSetAttribute(gemm_qkv,
                         cudaFuncAttributeMaxDynamicSharedMemorySize, gemm_smem);
    cudaFuncSetAttribute(gemm_single,
                         cudaFuncAttributeMaxDynamicSharedMemorySize, gemm_smem);
    const int attn_smem = (64 * LK + 64 * LV + 64 * LP) * 4;  // 87040
    cudaFuncSetAttribute(attn_tf32,
                         cudaFuncAttributeMaxDynamicSharedMemorySize, attn_smem);

    gemm_qkv<<<dim3(DIM / 128, SEQ / 128, 3), 256, gemm_smem>>>(
        x, Wq, bq, pq, Wk, bk, pk, Wv, bv, pv);

    build_cs_kernel<<<SEQ, CC>>>(fcos, fsin);
    rmsnorm_rope_kernel<<<SEQ, 384>>>(pq, nqw);
    rmsnorm_rope_kernel<<<SEQ, 384>>>(pk, nkw);

    attn_tf32<<<dim3(SEQ / 64, HEADS), 128, attn_smem>>>(pq, pk, pv, pa);

    gemm_single<<<dim3(DIM / 128, SEQ / 128), 256, gemm_smem>>>(pa, Wo, bo, out);
}